// round 12
// baseline (speedup 1.0000x reference)
#include <cuda_runtime.h>
#include <cstdint>

#define BB 64
#define TT 512
#define DD 768
#define MAXN 80
#define KMAX 68             // rel_err ~ 0.985*0.9^69 ~ 7.0e-4 (30% margin under 1e-3)
#define LOG2_DECAY (-0.15200309344504995f)  // log2(0.9)
#define CHUNK 8
#define NSTAGE 6
#define ROW_BYTES (DD * 4)                   // 3072
#define STAGE_FLOATS (CHUNK * DD)            // 6144
#define STAGE_BYTES (CHUNK * ROW_BYTES)      // 24576
#define DYN_SMEM (NSTAGE * STAGE_BYTES)      // 147456

// cross-block handshake flags (zero-init; consumer resets after use -> replay-safe)
__device__ int g_flag[BB];

__device__ __forceinline__ uint32_t smem_u32(const void* p) {
    return (uint32_t)__cvta_generic_to_shared(p);
}
__device__ __forceinline__ void mbar_init(uint32_t mb, uint32_t cnt) {
    asm volatile("mbarrier.init.shared.b64 [%0], %1;" :: "r"(mb), "r"(cnt) : "memory");
}
__device__ __forceinline__ void mbar_arrive_tx(uint32_t mb, uint32_t bytes) {
    asm volatile("mbarrier.arrive.expect_tx.shared.b64 _, [%0], %1;"
                 :: "r"(mb), "r"(bytes) : "memory");
}
__device__ __forceinline__ void mbar_arrive(uint32_t mb) {
    asm volatile("mbarrier.arrive.shared.b64 _, [%0];" :: "r"(mb) : "memory");
}
__device__ __forceinline__ void bulk_ld(uint32_t dst, const void* src, uint32_t bytes,
                                        uint32_t mb) {
    asm volatile("cp.async.bulk.shared::cta.global.mbarrier::complete_tx::bytes "
                 "[%0], [%1], %2, [%3];"
                 :: "r"(dst), "l"(src), "r"(bytes), "r"(mb) : "memory");
}
__device__ __forceinline__ void mbar_wait(uint32_t mb, uint32_t phase) {
    asm volatile(
        "{\n\t.reg .pred P;\n\t"
        "W_%=:\n\t"
        "mbarrier.try_wait.parity.acquire.cta.shared::cta.b64 P, [%0], %1, 0x989680;\n\t"
        "@!P bra W_%=;\n\t}"
        :: "r"(mb), "r"(phase) : "memory");
}

// Grid (BB, 2), 768 threads. One block per (batch, stream).
__global__ void __launch_bounds__(DD, 1) fused_kernel(
    const float* __restrict__ spk_hist, const float* __restrict__ spk_mask,
    const float* __restrict__ act_hist, const float* __restrict__ act_mask,
    const float* __restrict__ spk_mean, const float* __restrict__ act_mean,
    const float* __restrict__ mix_logits, float* __restrict__ out)
{
    extern __shared__ float sbuf[];   // NSTAGE x CHUNK x 768 floats

    const int b = blockIdx.x, s = blockIdx.y;
    const int tid = threadIdx.x;
    const int wid = tid >> 5, lane = tid & 31;

    const float* mask = (s == 0) ? spk_mask : act_mask;
    const float* X    = (s == 0) ? spk_hist : act_hist;
    const float* mean = (s == 0) ? spk_mean : act_mean;

    __shared__ int   sidx[MAXN];
    __shared__ float swt[MAXN];
    __shared__ int   wcnt[16];
    __shared__ int   kcnt[16];
    __shared__ __align__(8) unsigned long long mbar_store[NSTAGE];

    if (tid < NSTAGE) mbar_init(smem_u32(&mbar_store[tid]), CHUNK);

    // ---- Phase 1: weights via ballot suffix-scan ----
    int m = 0;
    if (tid < TT) m = (mask[b * TT + tid] > 0.5f) ? 1 : 0;
    unsigned bal = __ballot_sync(0xFFFFFFFFu, m);
    if (lane == 0 && wid < 16) wcnt[wid] = __popc(bal);
    __syncthreads();   // also fences mbarrier init

    int after = __popc(bal & (0xFFFFFFFEu << lane));
    int total = 0;
    #pragma unroll
    for (int i = 0; i < 16; i++) {
        int c = wcnt[i];
        total += c;
        if (i > wid) after += c;
    }
    int k = after;
    int keep = (tid < TT && m && k <= KMAX) ? 1 : 0;
    float w = keep ? 0.1f * exp2f((float)k * LOG2_DECAY) : 0.0f;

    unsigned kb = __ballot_sync(0xFFFFFFFFu, keep);
    if (lane == 0 && wid < 16) kcnt[wid] = __popc(kb);
    __syncthreads();

    int pos = __popc(kb & ((1u << lane) - 1u));
    int n = 0;
    #pragma unroll
    for (int i = 0; i < 16; i++) {
        int c = kcnt[i];
        if (i < wid) pos += c;
        n += c;
    }
    if (keep) {
        sidx[pos] = tid;
        swt[pos]  = w;
    }
    __syncthreads();

    // ---- Phase 2: NSTAGE-deep bulk ring, PARALLEL issuance (8 issuers/stage) ----
    const char* rowbase = (const char*)(X + (size_t)b * TT * DD);
    const uint32_t sb_base = smem_u32(sbuf);
    const int nch = (n + CHUNK - 1) / CHUNK;
    float acc0 = 0.0f, acc1 = 0.0f;

    // prologue: threads 0..7 each issue their row for every live stage
    if (tid < CHUNK) {
        #pragma unroll
        for (int kc = 0; kc < NSTAGE; kc++) {
            int r0 = kc * CHUNK;
            if (r0 >= n) break;
            uint32_t mb = smem_u32(&mbar_store[kc]);
            int rows = n - r0; if (rows > CHUNK) rows = CHUNK;
            if (tid < rows) {
                mbar_arrive_tx(mb, ROW_BYTES);
                bulk_ld(sb_base + kc * STAGE_BYTES + tid * ROW_BYTES,
                        rowbase + (size_t)sidx[r0 + tid] * ROW_BYTES, ROW_BYTES, mb);
            } else {
                mbar_arrive(mb);
            }
        }
    }

    for (int kc = 0; kc < nch; kc++) {
        const int slot = kc % NSTAGE;
        mbar_wait(smem_u32(&mbar_store[slot]), (kc / NSTAGE) & 1);

        const float* bp = sbuf + slot * STAGE_FLOATS + tid;
        const int base = kc * CHUNK;
        const int rows = (n - base < CHUNK) ? (n - base) : CHUNK;
        if (rows == CHUNK) {
            acc0 += swt[base + 0] * bp[0 * DD];
            acc1 += swt[base + 1] * bp[1 * DD];
            acc0 += swt[base + 2] * bp[2 * DD];
            acc1 += swt[base + 3] * bp[3 * DD];
            acc0 += swt[base + 4] * bp[4 * DD];
            acc1 += swt[base + 5] * bp[5 * DD];
            acc0 += swt[base + 6] * bp[6 * DD];
            acc1 += swt[base + 7] * bp[7 * DD];
        } else {
            for (int i = 0; i < rows; i++)
                acc0 += swt[base + i] * bp[i * DD];
        }
        __syncthreads();   // all threads done with this stage

        // refill slot with chunk kc+NSTAGE (8 parallel issuers)
        int r0 = (kc + NSTAGE) * CHUNK;
        if (tid < CHUNK && r0 < n) {
            uint32_t mb = smem_u32(&mbar_store[slot]);
            int rows2 = n - r0; if (rows2 > CHUNK) rows2 = CHUNK;
            if (tid < rows2) {
                mbar_arrive_tx(mb, ROW_BYTES);
                bulk_ld(sb_base + slot * STAGE_BYTES + tid * ROW_BYTES,
                        rowbase + (size_t)sidx[r0 + tid] * ROW_BYTES, ROW_BYTES, mb);
            } else {
                mbar_arrive(mb);
            }
        }
    }

    float cval = (total > 0) ? (acc0 + acc1) : mean[(size_t)b * DD + tid];

    // softmax mix weights
    float l0 = mix_logits[0], l1 = mix_logits[1];
    float mx = fmaxf(l0, l1);
    float e0 = expf(l0 - mx), e1 = expf(l1 - mx);
    float inv = 1.0f / (e0 + e1);
    float w0m = e0 * inv, w1m = e1 * inv;

    // ---- Phase 3: publish / consume / mix ----
    if (s == 0) {
        out[(size_t)(BB + b) * DD + tid] = cval;            // c_spk
        __syncthreads();
        if (tid == 0) {
            __threadfence();
            atomicExch(&g_flag[b], 1);
        }
    } else {
        out[(size_t)(2 * BB + b) * DD + tid] = cval;        // c_act
        if (tid == 0) {
            while (atomicAdd(&g_flag[b], 0) == 0) { }
            atomicExch(&g_flag[b], 0);   // reset for next graph replay
            __threadfence();
        }
        __syncthreads();
        float cs = out[(size_t)(BB + b) * DD + tid];
        out[(size_t)b * DD + tid] = w0m * cs + w1m * cval;  // c
        if (b == 0 && tid < 2) out[3 * BB * DD + tid] = (tid == 0) ? w0m : w1m;  // w
    }
}

extern "C" void kernel_launch(void* const* d_in, const int* in_sizes, int n_in,
                              void* d_out, int out_size) {
    const float* spk_hist   = (const float*)d_in[0];
    const float* spk_mask   = (const float*)d_in[1];
    const float* act_hist   = (const float*)d_in[2];
    const float* act_mask   = (const float*)d_in[3];
    const float* spk_mean   = (const float*)d_in[4];
    const float* act_mean   = (const float*)d_in[5];
    const float* mix_logits = (const float*)d_in[6];
    float* out = (float*)d_out;

    cudaFuncSetAttribute(fused_kernel,
                         cudaFuncAttributeMaxDynamicSharedMemorySize, DYN_SMEM);
    fused_kernel<<<dim3(BB, 2), DD, DYN_SMEM>>>(spk_hist, spk_mask, act_hist, act_mask,
                                                spk_mean, act_mean, mix_logits, out);
}

// round 13
// speedup vs baseline: 1.3125x; 1.3125x over previous
#include <cuda_runtime.h>
#include <cstdint>

#define BB 64
#define TT 512
#define DD 768
#define NC (DD / 4)          // 192 float4 columns
#define NTHR 192
#define ZS 4                 // t-list split factor (blocks per (b,s))
#define MAXN 80
#define KMAX 68              // rel_err ~ 0.985*0.9^69 ~ 7.0e-4 (30% margin under 1e-3)
#define LOG2_DECAY (-0.15200309344504995f)  // log2(0.9)

__device__ __forceinline__ void fma4(float4& a, float w, const float4& v) {
    a.x += w * v.x; a.y += w * v.y; a.z += w * v.z; a.w += w * v.w;
}

// Grid (BB, 2, ZS), 192 threads. Outputs accumulated via REDG into zeroed d_out.
__global__ void __launch_bounds__(NTHR) fused_kernel(
    const float* __restrict__ spk_hist, const float* __restrict__ spk_mask,
    const float* __restrict__ act_hist, const float* __restrict__ act_mask,
    const float* __restrict__ spk_mean, const float* __restrict__ act_mean,
    const float* __restrict__ mix_logits, float* __restrict__ out)
{
    const int b = blockIdx.x, s = blockIdx.y, z = blockIdx.z;
    const int tid = threadIdx.x;
    const int wid = tid >> 5, lane = tid & 31;

    const float* mask = (s == 0) ? spk_mask : act_mask;
    const float* X    = (s == 0) ? spk_hist : act_hist;
    const float* mean = (s == 0) ? spk_mean : act_mean;

    __shared__ unsigned bits[16], kbits[16];
    __shared__ int suf[17];    // suffix popc of mask bits
    __shared__ int pref[17];   // exclusive prefix popc of keep bits, pref[16] = n
    __shared__ int   sidx[MAXN];
    __shared__ float swt[MAXN];

    // ---- Phase 1: mask bitmask (3 passes of 192 threads over T=512) ----
    #pragma unroll
    for (int p = 0; p < 3; p++) {
        int t = p * NTHR + tid;
        int m = (t < TT) ? (mask[b * TT + t] > 0.5f ? 1 : 0) : 0;
        unsigned bal = __ballot_sync(0xFFFFFFFFu, m);
        int w = 6 * p + wid;
        if (lane == 0 && w < 16) bits[w] = bal;
    }
    __syncthreads();
    if (wid == 0) {   // suffix-sum of per-word popcounts via shfl
        int c = (lane < 16) ? __popc(bits[lane]) : 0;
        int x = c;
        #pragma unroll
        for (int off = 1; off < 16; off <<= 1) {
            int y = __shfl_down_sync(0xFFFFFFFFu, x, off);
            if (lane + off < 16) x += y;
        }
        if (lane < 16) suf[lane] = x;
        if (lane == 0) suf[16] = 0;
    }
    __syncthreads();
    const int total = suf[0];

    int   keepf[3];
    float wt[3];
    #pragma unroll
    for (int p = 0; p < 3; p++) {
        int t = p * NTHR + tid;
        int w = 6 * p + wid;
        int m = 0, k = 0;
        if (t < TT) {
            unsigned word = bits[w];
            m = (word >> lane) & 1u;
            k = suf[w + 1] + __popc(word & (0xFFFFFFFEu << lane));
        }
        int keep = (m && k <= KMAX) ? 1 : 0;
        keepf[p] = keep;
        wt[p] = keep ? 0.1f * exp2f((float)k * LOG2_DECAY) : 0.0f;
        unsigned kb = __ballot_sync(0xFFFFFFFFu, keep);
        if (lane == 0 && w < 16) kbits[w] = kb;
    }
    __syncthreads();
    if (wid == 0) {   // exclusive prefix of keep popcounts via shfl
        int c = (lane < 16) ? __popc(kbits[lane]) : 0;
        int x = c;
        #pragma unroll
        for (int off = 1; off < 16; off <<= 1) {
            int y = __shfl_up_sync(0xFFFFFFFFu, x, off);
            if (lane >= off) x += y;
        }
        if (lane < 16) pref[lane] = x - c;
        if (lane == 15) pref[16] = x;
    }
    __syncthreads();
    const int n = pref[16];

    #pragma unroll
    for (int p = 0; p < 3; p++) {
        if (keepf[p]) {
            int t = p * NTHR + tid;
            int w = 6 * p + wid;
            int pos = pref[w] + __popc(kbits[w] & ((1u << lane) - 1u));
            sidx[pos] = t;
            swt[pos]  = wt[p];
        }
    }
    __syncthreads();

    // ---- Phase 2: weighted sum over stride-ZS slice; thread owns float4 col ----
    const float4* base = (const float4*)(X + (size_t)b * TT * DD) + tid;
    float4 acc = make_float4(0.f, 0.f, 0.f, 0.f);
    int j = z;
    for (; j + 3 * ZS < n; j += 4 * ZS) {
        int   t0 = sidx[j],          t1 = sidx[j + ZS];
        int   t2 = sidx[j + 2 * ZS], t3 = sidx[j + 3 * ZS];
        float w0 = swt[j],           w1 = swt[j + ZS];
        float w2 = swt[j + 2 * ZS],  w3 = swt[j + 3 * ZS];
        float4 v0 = base[(size_t)t0 * NC];
        float4 v1 = base[(size_t)t1 * NC];
        float4 v2 = base[(size_t)t2 * NC];
        float4 v3 = base[(size_t)t3 * NC];
        fma4(acc, w0, v0); fma4(acc, w1, v1); fma4(acc, w2, v2); fma4(acc, w3, v3);
    }
    for (; j < n; j += ZS) {
        float4 v = base[(size_t)sidx[j] * NC];
        fma4(acc, swt[j], v);
    }

    // ---- Phase 3: direct REDG accumulation into zeroed out buffer ----
    // mean fallback: only the z==0 block contributes mean; others contribute 0.
    if (total == 0) {
        if (z == 0) acc = ((const float4*)(mean + (size_t)b * DD))[tid];
        else        acc = make_float4(0.f, 0.f, 0.f, 0.f);
    }

    float l0 = mix_logits[0], l1 = mix_logits[1];
    float mx = fmaxf(l0, l1);
    float e0 = expf(l0 - mx), e1 = expf(l1 - mx);
    float inv = 1.0f / (e0 + e1);
    float w0m = e0 * inv, w1m = e1 * inv;
    float wsel = (s == 0) ? w0m : w1m;

    float* dst_s = out + (size_t)(BB * (1 + s) + b) * DD + tid * 4;  // c_spk / c_act
    float* dst_c = out + (size_t)b * DD + tid * 4;                    // c
    atomicAdd(dst_s + 0, acc.x);
    atomicAdd(dst_s + 1, acc.y);
    atomicAdd(dst_s + 2, acc.z);
    atomicAdd(dst_s + 3, acc.w);
    atomicAdd(dst_c + 0, wsel * acc.x);
    atomicAdd(dst_c + 1, wsel * acc.y);
    atomicAdd(dst_c + 2, wsel * acc.z);
    atomicAdd(dst_c + 3, wsel * acc.w);

    if (b == 0 && s == 0 && z == 0 && tid < 2)
        out[3 * BB * DD + tid] = (tid == 0) ? w0m : w1m;   // w (unique writer)
}

extern "C" void kernel_launch(void* const* d_in, const int* in_sizes, int n_in,
                              void* d_out, int out_size) {
    const float* spk_hist   = (const float*)d_in[0];
    const float* spk_mask   = (const float*)d_in[1];
    const float* act_hist   = (const float*)d_in[2];
    const float* act_mask   = (const float*)d_in[3];
    const float* spk_mean   = (const float*)d_in[4];
    const float* act_mean   = (const float*)d_in[5];
    const float* mix_logits = (const float*)d_in[6];
    float* out = (float*)d_out;

    // zero accumulation targets (graph-capturable async memset, no allocation)
    cudaMemsetAsync(d_out, 0, (size_t)out_size * sizeof(float));

    fused_kernel<<<dim3(BB, 2, ZS), NTHR>>>(spk_hist, spk_mask, act_hist, act_mask,
                                            spk_mean, act_mean, mix_logits, out);
}

// round 14
// speedup vs baseline: 1.3164x; 1.0030x over previous
#include <cuda_runtime.h>
#include <cstdint>

#define BB 64
#define TT 512
#define DD 768
#define NC (DD / 4)          // 192 float4 columns
#define NTHR 192
#define ZS 4                 // t-list split factor (blocks per (b,s))
#define MAXN 80
#define KMAX 68              // rel_err ~ 0.985*0.9^69 ~ 7.0e-4 (30% margin under 1e-3)
#define LOG2_DECAY (-0.15200309344504995f)  // log2(0.9)

__device__ __forceinline__ void fma4(float4& a, float w, const float4& v) {
    a.x += w * v.x; a.y += w * v.y; a.z += w * v.z; a.w += w * v.w;
}

// Grid (BB, 2, ZS), 192 threads. Outputs accumulated via REDG into zeroed d_out.
// launch_bounds(192, 3): reg cap ~113 so the 8-wide load batch stays register-resident.
__global__ void __launch_bounds__(NTHR, 3) fused_kernel(
    const float* __restrict__ spk_hist, const float* __restrict__ spk_mask,
    const float* __restrict__ act_hist, const float* __restrict__ act_mask,
    const float* __restrict__ spk_mean, const float* __restrict__ act_mean,
    const float* __restrict__ mix_logits, float* __restrict__ out)
{
    const int b = blockIdx.x, s = blockIdx.y, z = blockIdx.z;
    const int tid = threadIdx.x;
    const int wid = tid >> 5, lane = tid & 31;

    const float* mask = (s == 0) ? spk_mask : act_mask;
    const float* X    = (s == 0) ? spk_hist : act_hist;
    const float* mean = (s == 0) ? spk_mean : act_mean;

    __shared__ unsigned bits[16], kbits[16];
    __shared__ int suf[17];    // suffix popc of mask bits
    __shared__ int pref[17];   // exclusive prefix popc of keep bits, pref[16] = n
    __shared__ int   sidx[MAXN];
    __shared__ float swt[MAXN];

    // ---- Phase 1: mask bitmask (3 passes of 192 threads over T=512) ----
    #pragma unroll
    for (int p = 0; p < 3; p++) {
        int t = p * NTHR + tid;
        int m = (t < TT) ? (mask[b * TT + t] > 0.5f ? 1 : 0) : 0;
        unsigned bal = __ballot_sync(0xFFFFFFFFu, m);
        int w = 6 * p + wid;
        if (lane == 0 && w < 16) bits[w] = bal;
    }
    __syncthreads();
    if (wid == 0) {   // suffix-sum of per-word popcounts via shfl
        int c = (lane < 16) ? __popc(bits[lane]) : 0;
        int x = c;
        #pragma unroll
        for (int off = 1; off < 16; off <<= 1) {
            int y = __shfl_down_sync(0xFFFFFFFFu, x, off);
            if (lane + off < 16) x += y;
        }
        if (lane < 16) suf[lane] = x;
        if (lane == 0) suf[16] = 0;
    }
    __syncthreads();
    const int total = suf[0];

    int   keepf[3];
    float wt[3];
    #pragma unroll
    for (int p = 0; p < 3; p++) {
        int t = p * NTHR + tid;
        int w = 6 * p + wid;
        int m = 0, k = 0;
        if (t < TT) {
            unsigned word = bits[w];
            m = (word >> lane) & 1u;
            k = suf[w + 1] + __popc(word & (0xFFFFFFFEu << lane));
        }
        int keep = (m && k <= KMAX) ? 1 : 0;
        keepf[p] = keep;
        wt[p] = keep ? 0.1f * exp2f((float)k * LOG2_DECAY) : 0.0f;
        unsigned kb = __ballot_sync(0xFFFFFFFFu, keep);
        if (lane == 0 && w < 16) kbits[w] = kb;
    }
    __syncthreads();
    if (wid == 0) {   // exclusive prefix of keep popcounts via shfl
        int c = (lane < 16) ? __popc(kbits[lane]) : 0;
        int x = c;
        #pragma unroll
        for (int off = 1; off < 16; off <<= 1) {
            int y = __shfl_up_sync(0xFFFFFFFFu, x, off);
            if (lane >= off) x += y;
        }
        if (lane < 16) pref[lane] = x - c;
        if (lane == 15) pref[16] = x;
    }
    __syncthreads();
    const int n = pref[16];

    #pragma unroll
    for (int p = 0; p < 3; p++) {
        if (keepf[p]) {
            int t = p * NTHR + tid;
            int w = 6 * p + wid;
            int pos = pref[w] + __popc(kbits[w] & ((1u << lane) - 1u));
            sidx[pos] = t;
            swt[pos]  = wt[p];
        }
    }
    __syncthreads();

    // ---- Phase 2: weighted sum, 8-wide register-resident batches ----
    const float4* base = (const float4*)(X + (size_t)b * TT * DD) + tid;
    float4 acc = make_float4(0.f, 0.f, 0.f, 0.f);
    int j = z;
    #pragma unroll 1
    for (; j + 7 * ZS < n; j += 8 * ZS) {
        int   t0 = sidx[j],          t1 = sidx[j + ZS];
        int   t2 = sidx[j + 2 * ZS], t3 = sidx[j + 3 * ZS];
        int   t4 = sidx[j + 4 * ZS], t5 = sidx[j + 5 * ZS];
        int   t6 = sidx[j + 6 * ZS], t7 = sidx[j + 7 * ZS];
        float w0 = swt[j],           w1 = swt[j + ZS];
        float w2 = swt[j + 2 * ZS],  w3 = swt[j + 3 * ZS];
        float w4 = swt[j + 4 * ZS],  w5 = swt[j + 5 * ZS];
        float w6 = swt[j + 6 * ZS],  w7 = swt[j + 7 * ZS];
        float4 v0 = base[(size_t)t0 * NC];
        float4 v1 = base[(size_t)t1 * NC];
        float4 v2 = base[(size_t)t2 * NC];
        float4 v3 = base[(size_t)t3 * NC];
        float4 v4 = base[(size_t)t4 * NC];
        float4 v5 = base[(size_t)t5 * NC];
        float4 v6 = base[(size_t)t6 * NC];
        float4 v7 = base[(size_t)t7 * NC];
        fma4(acc, w0, v0); fma4(acc, w1, v1); fma4(acc, w2, v2); fma4(acc, w3, v3);
        fma4(acc, w4, v4); fma4(acc, w5, v5); fma4(acc, w6, v6); fma4(acc, w7, v7);
    }
    for (; j < n; j += ZS) {
        float4 v = base[(size_t)sidx[j] * NC];
        fma4(acc, swt[j], v);
    }

    // ---- Phase 3: direct REDG accumulation into zeroed out buffer ----
    if (total == 0) {
        if (z == 0) acc = ((const float4*)(mean + (size_t)b * DD))[tid];
        else        acc = make_float4(0.f, 0.f, 0.f, 0.f);
    }

    float l0 = mix_logits[0], l1 = mix_logits[1];
    float mx = fmaxf(l0, l1);
    float e0 = expf(l0 - mx), e1 = expf(l1 - mx);
    float inv = 1.0f / (e0 + e1);
    float w0m = e0 * inv, w1m = e1 * inv;
    float wsel = (s == 0) ? w0m : w1m;

    float* dst_s = out + (size_t)(BB * (1 + s) + b) * DD + tid * 4;  // c_spk / c_act
    float* dst_c = out + (size_t)b * DD + tid * 4;                    // c
    atomicAdd(dst_s + 0, acc.x);
    atomicAdd(dst_s + 1, acc.y);
    atomicAdd(dst_s + 2, acc.z);
    atomicAdd(dst_s + 3, acc.w);
    atomicAdd(dst_c + 0, wsel * acc.x);
    atomicAdd(dst_c + 1, wsel * acc.y);
    atomicAdd(dst_c + 2, wsel * acc.z);
    atomicAdd(dst_c + 3, wsel * acc.w);

    if (b == 0 && s == 0 && z == 0 && tid < 2)
        out[3 * BB * DD + tid] = (tid == 0) ? w0m : w1m;   // w (unique writer)
}

extern "C" void kernel_launch(void* const* d_in, const int* in_sizes, int n_in,
                              void* d_out, int out_size) {
    const float* spk_hist   = (const float*)d_in[0];
    const float* spk_mask   = (const float*)d_in[1];
    const float* act_hist   = (const float*)d_in[2];
    const float* act_mask   = (const float*)d_in[3];
    const float* spk_mean   = (const float*)d_in[4];
    const float* act_mean   = (const float*)d_in[5];
    const float* mix_logits = (const float*)d_in[6];
    float* out = (float*)d_out;

    // zero accumulation targets (graph-capturable async memset, no allocation)
    cudaMemsetAsync(d_out, 0, (size_t)out_size * sizeof(float));

    fused_kernel<<<dim3(BB, 2, ZS), NTHR>>>(spk_hist, spk_mask, act_hist, act_mask,
                                            spk_mean, act_mean, mix_logits, out);
}